// round 8
// baseline (speedup 1.0000x reference)
#include <cuda_runtime.h>
#include <math.h>

#define BB 128
#define PP 8732
#define MM 16
#define CC 3
#define NT 256
#define NW (NT / 32)

// Cross-CTA accumulators (device globals: no allocation).
__device__ double g_conf_sum;
__device__ double g_l1_sum;
__device__ int    g_npos;

__global__ void mbl_init_kernel() {
    g_conf_sum = 0.0;
    g_l1_sum   = 0.0;
    g_npos     = 0;
}

__device__ __forceinline__ float block_sum_f(float v, volatile float* sh, int tid) {
#pragma unroll
    for (int o = 16; o; o >>= 1) v += __shfl_down_sync(0xffffffffu, v, o);
    if ((tid & 31) == 0) sh[tid >> 5] = v;
    __syncthreads();
    if (tid == 0) {
        float s = 0.f;
        for (int w = 0; w < NW; w++) s += sh[w];
        sh[0] = s;
    }
    __syncthreads();
    float r = sh[0];
    __syncthreads();
    return r;
}

__device__ __forceinline__ int block_sum_i(int v, volatile int* sh, int tid) {
#pragma unroll
    for (int o = 16; o; o >>= 1) v += __shfl_down_sync(0xffffffffu, v, o);
    if ((tid & 31) == 0) sh[tid >> 5] = v;
    __syncthreads();
    if (tid == 0) {
        int s = 0;
        for (int w = 0; w < NW; w++) s += sh[w];
        sh[0] = s;
    }
    __syncthreads();
    int r = sh[0];
    __syncthreads();
    return r;
}

// Stable logaddexp(0, x) = max(x,0) + log1p(exp(-|x|))
__device__ __forceinline__ float softplusf(float x) {
    return fmaxf(x, 0.f) + log1pf(expf(-fabsf(x)));
}

__global__ __launch_bounds__(NT) void mbl_kernel(
    const float* __restrict__ plocs,    // (B,P,4)
    const float* __restrict__ pscores,  // (B,P,C)
    const float* __restrict__ boxes,    // (B,M,4) xyxy
    const int*   __restrict__ labels,   // (B,M)
    const float* __restrict__ priors,   // (P,4) cxcy
    float* __restrict__ out, int out_size)
{
    extern __shared__ char smem_raw[];
    float*         conf_neg  = (float*)smem_raw;                 // P floats
    float*         ov_prior  = conf_neg + PP;                    // P floats
    float*         sboxes    = ov_prior + PP;                    // 64 floats
    int*           slabels   = (int*)(sboxes + 64);              // 16
    float*         wbv       = (float*)(slabels + 16);           // MM*NW
    int*           wbi       = (int*)(wbv + MM * NW);            // MM*NW
    int*           sprior_obj= wbi + MM * NW;                    // 16
    float*         redf      = (float*)(sprior_obj + 16);        // 32
    int*           redi      = (int*)(redf + 32);                // 32
    unsigned char* obj_prior = (unsigned char*)(redi + 32);      // P bytes

    const int i   = blockIdx.x;
    const int tid = threadIdx.x;

    // Load this row's boxes + labels
    if (tid < MM * 4) sboxes[tid]  = boxes[i * MM * 4 + tid];
    if (tid < MM)     slabels[tid] = labels[i * MM + tid];
    __syncthreads();

    // ---- Pass 1: IoU matching ----
    float bestv[MM];
    int   besti[MM];
#pragma unroll
    for (int m = 0; m < MM; m++) { bestv[m] = -1.0f; besti[m] = 0x7fffffff; }

    for (int p = tid; p < PP; p += NT) {
        float4 pr = ((const float4*)priors)[p];
        float px1 = pr.x - pr.z / 2.0f;
        float py1 = pr.y - pr.w / 2.0f;
        float px2 = pr.x + pr.z / 2.0f;
        float py2 = pr.y + pr.w / 2.0f;
        float ab  = (px2 - px1) * (py2 - py1);

        float bv = -1.0f; int bm = 0;
#pragma unroll
        for (int m = 0; m < MM; m++) {
            float bx1 = sboxes[m * 4 + 0], by1 = sboxes[m * 4 + 1];
            float bx2 = sboxes[m * 4 + 2], by2 = sboxes[m * 4 + 3];
            float iw = fmaxf(fminf(bx2, px2) - fmaxf(bx1, px1), 0.f);
            float ih = fmaxf(fminf(by2, py2) - fmaxf(by1, py1), 0.f);
            float inter = iw * ih;
            float aa = (bx2 - bx1) * (by2 - by1);
            float iou = inter / (aa + ab - inter);
            if (iou > bv) { bv = iou; bm = m; }                      // first-max (argmax axis=0)
            if (iou > bestv[m]) { bestv[m] = iou; besti[m] = p; }    // first-max within thread
        }
        ov_prior[p]  = bv;
        obj_prior[p] = (unsigned char)bm;
    }

    // Reduce per-object bests: warp shuffle, then cross-warp (tie -> smallest prior index)
#pragma unroll
    for (int m = 0; m < MM; m++) {
        float v = bestv[m]; int ix = besti[m];
#pragma unroll
        for (int o = 16; o; o >>= 1) {
            float v2 = __shfl_down_sync(0xffffffffu, v, o);
            int   i2 = __shfl_down_sync(0xffffffffu, ix, o);
            if (v2 > v || (v2 == v && i2 < ix)) { v = v2; ix = i2; }
        }
        if ((tid & 31) == 0) { wbv[m * NW + (tid >> 5)] = v; wbi[m * NW + (tid >> 5)] = ix; }
    }
    __syncthreads();
    if (tid < MM) {
        float v = wbv[tid * NW]; int ix = wbi[tid * NW];
        for (int w = 1; w < NW; w++) {
            float v2 = wbv[tid * NW + w]; int i2 = wbi[tid * NW + w];
            if (v2 > v || (v2 == v && i2 < ix)) { v = v2; ix = i2; }
        }
        sprior_obj[tid] = ix;
    }
    __syncthreads();
    // Bipartite overrides (sequential m: last object wins on duplicate priors)
    if (tid == 0) {
        for (int m = 0; m < MM; m++) {
            int p = sprior_obj[m];
            obj_prior[p] = (unsigned char)m;
            ov_prior[p]  = 1.0f;
        }
    }
    __syncthreads();

    // ---- Pass 2: labels, BCE, L1, conf_neg ----
    int   npos_loc = 0;
    float cpos_loc = 0.f, l1_loc = 0.f;

    for (int p = tid; p < PP; p += NT) {
        int m   = obj_prior[p];
        int lab = (ov_prior[p] < 0.5f) ? 0 : slabels[m];

        const float* sc = pscores + ((size_t)i * PP + p) * CC;
        float s0 = sc[0], s1 = sc[1], s2 = sc[2];
        // target: lab 0->[1,0,0] 1->[0,1,0] 2->[0,0,1] 3->[0,1,1]
        float t0 = (lab == 0) ? 1.f : 0.f;
        float t1 = (lab == 1 || lab == 3) ? 1.f : 0.f;
        float t2 = (lab == 2 || lab == 3) ? 1.f : 0.f;
        float bce = (softplusf(s0) - s0 * t0)
                  + (softplusf(s1) - s1 * t1)
                  + (softplusf(s2) - s2 * t2);

        if (lab > 0) {
            npos_loc++;
            cpos_loc += bce;
            conf_neg[p] = 0.f;
            const float* pl = plocs + ((size_t)i * PP + p) * 4;
            float4 pr = ((const float4*)priors)[p];
            float bx1 = sboxes[m * 4 + 0], by1 = sboxes[m * 4 + 1];
            float bx2 = sboxes[m * 4 + 2], by2 = sboxes[m * 4 + 3];
            float cx = (bx1 + bx2) / 2.0f, cy = (by1 + by2) / 2.0f;
            float w  = bx2 - bx1,          h  = by2 - by1;
            float g0 = (cx - pr.x) / (pr.z / 10.0f);
            float g1 = (cy - pr.y) / (pr.w / 10.0f);
            float g2 = logf(w / pr.z) * 5.0f;
            float g3 = logf(h / pr.w) * 5.0f;
            l1_loc += fabsf(pl[0] - g0) + fabsf(pl[1] - g1)
                    + fabsf(pl[2] - g2) + fabsf(pl[3] - g3);
        } else {
            conf_neg[p] = bce;
        }
    }
    __syncthreads();

    int   npos_i = block_sum_i(npos_loc, redi, tid);
    float cpos_i = block_sum_f(cpos_loc, redf, tid);
    float l1_i   = block_sum_f(l1_loc,  redf, tid);

    // ---- Hard-negative mining: exact top-k sum via bitwise binary search ----
    int k = 3 * npos_i;
    if (k > PP) k = PP;
    float hardneg = 0.f;
    if (k > 0) {
        unsigned lo = 0u, hi = 0x7f800000u;  // [0, +inf): conf_neg >= 0, finite
        while (hi - lo > 1u) {
            unsigned mid = (lo + hi) >> 1;
            float tv = __uint_as_float(mid);
            int c = 0;
            for (int p = tid; p < PP; p += NT) c += (conf_neg[p] >= tv) ? 1 : 0;
            c = block_sum_i(c, redi, tid);
            if (c >= k) lo = mid; else hi = mid;
        }
        float t = __uint_as_float(lo);  // exact k-th largest value
        int cgt = 0; float sgt = 0.f;
        for (int p = tid; p < PP; p += NT) {
            float v = conf_neg[p];
            if (v > t) { cgt++; sgt += v; }
        }
        cgt = block_sum_i(cgt, redi, tid);
        sgt = block_sum_f(sgt, redf, tid);
        hardneg = sgt + t * (float)(k - cgt);  // ties at t exactly reproduce sorted top-k
    }

    if (tid == 0) {
        atomicAdd(&g_conf_sum, (double)(cpos_i + hardneg));
        atomicAdd(&g_l1_sum,   (double)l1_i);
        atomicAdd(&g_npos,     npos_i);
        if (out_size >= 3 + BB) out[3 + i] = (float)npos_i;
    }
}

__global__ void mbl_fin_kernel(float* __restrict__ out, int out_size) {
    double npt  = (double)g_npos;
    double conf = g_conf_sum / (1e-10 + npt);
    double loc  = (g_npos > 0) ? (g_l1_sum / (4.0 * fmax(npt, 1.0))) : 0.0;
    out[0] = (float)(conf + loc);
    if (out_size > 1) out[1] = (float)conf;
    if (out_size > 2) out[2] = (float)loc;
}

extern "C" void kernel_launch(void* const* d_in, const int* in_sizes, int n_in,
                              void* d_out, int out_size) {
    const float* plocs   = (const float*)d_in[0];
    const float* pscores = (const float*)d_in[1];
    const float* boxes   = (const float*)d_in[2];
    const int*   labels  = (const int*)d_in[3];
    const float* priors  = (const float*)d_in[4];
    float* out = (float*)d_out;

    size_t shbytes = (size_t)PP * 4 * 2                       // conf_neg + ov_prior
                   + 4 * (64 + 16 + MM * NW * 2 + 16 + 32 + 32) // boxes/labels/reduce scratch
                   + PP;                                       // obj_prior bytes
    cudaFuncSetAttribute(mbl_kernel, cudaFuncAttributeMaxDynamicSharedMemorySize,
                         (int)shbytes);

    mbl_init_kernel<<<1, 1>>>();
    mbl_kernel<<<BB, NT, shbytes>>>(plocs, pscores, boxes, labels, priors, out, out_size);
    mbl_fin_kernel<<<1, 1>>>(out, out_size);
}

// round 9
// speedup vs baseline: 2.7028x; 2.7028x over previous
#include <cuda_runtime.h>
#include <math.h>

#define BB 128
#define PP 8732
#define MM 16
#define CC 3
#define NT 256
#define NW (NT / 32)

// Cross-CTA accumulators (device globals: no allocation).
__device__ double g_conf_sum;
__device__ double g_l1_sum;
__device__ int    g_npos;

__global__ void mbl_init_kernel() {
    g_conf_sum = 0.0;
    g_l1_sum   = 0.0;
    g_npos     = 0;
}

// Fast stable softplus: logaddexp(0,x) = max(x,0) + log(1 + exp(-|x|))
__device__ __forceinline__ float softplusf(float x) {
    float e = __expf(-fabsf(x));
    return fmaxf(x, 0.f) + __logf(1.0f + e);
}

__global__ __launch_bounds__(NT) void mbl_kernel(
    const float* __restrict__ plocs,    // (B,P,4)
    const float* __restrict__ pscores,  // (B,P,C)
    const float* __restrict__ boxes,    // (B,M,4) xyxy
    const int*   __restrict__ labels,   // (B,M)
    const float* __restrict__ priors,   // (P,4) cxcy
    float* __restrict__ out, int out_size)
{
    extern __shared__ char smem_raw[];
    float*         conf_neg  = (float*)smem_raw;                 // P floats
    float*         ov_prior  = conf_neg + PP;                    // P floats
    float*         sboxes    = ov_prior + PP;                    // 64 floats
    int*           slabels   = (int*)(sboxes + 64);              // 16
    float*         wbv       = (float*)(slabels + 16);           // MM*NW
    int*           wbi       = (int*)(wbv + MM * NW);            // MM*NW
    int*           sprior_obj= wbi + MM * NW;                    // 16
    int*           slotsI    = sprior_obj + 16;                  // 40 ints (pre-zeroed)
    float*         slotsF    = (float*)(slotsI + 40);            // 8 floats (pre-zeroed)
    unsigned char* obj_prior = (unsigned char*)(slotsF + 8);     // P bytes

    const int i    = blockIdx.x;
    const int tid  = threadIdx.x;
    const int lane = tid & 31;

    // Load this row's boxes + labels; zero reduction slots
    if (tid < MM * 4) sboxes[tid]  = boxes[i * MM * 4 + tid];
    if (tid < MM)     slabels[tid] = labels[i * MM + tid];
    if (tid < 40)     slotsI[tid]  = 0;
    if (tid >= 64 && tid < 72) slotsF[tid - 64] = 0.f;
    __syncthreads();

    // Hoist boxes into registers (invariant across the p-loop)
    float bx1[MM], by1[MM], bx2[MM], by2[MM], barea[MM];
#pragma unroll
    for (int m = 0; m < MM; m++) {
        bx1[m] = sboxes[m * 4 + 0];
        by1[m] = sboxes[m * 4 + 1];
        bx2[m] = sboxes[m * 4 + 2];
        by2[m] = sboxes[m * 4 + 3];
        barea[m] = (bx2[m] - bx1[m]) * (by2[m] - by1[m]);
    }

    // ---- Pass 1: IoU matching ----
    float bestv[MM];
    int   besti[MM];
#pragma unroll
    for (int m = 0; m < MM; m++) { bestv[m] = -1.0f; besti[m] = 0x7fffffff; }

    for (int p = tid; p < PP; p += NT) {
        float4 pr = ((const float4*)priors)[p];
        float px1 = pr.x - pr.z * 0.5f;
        float py1 = pr.y - pr.w * 0.5f;
        float px2 = pr.x + pr.z * 0.5f;
        float py2 = pr.y + pr.w * 0.5f;
        float ab  = pr.z * pr.w;

        float bv = -1.0f; int bm = 0;
#pragma unroll
        for (int m = 0; m < MM; m++) {
            float iw = fmaxf(fminf(bx2[m], px2) - fmaxf(bx1[m], px1), 0.f);
            float ih = fmaxf(fminf(by2[m], py2) - fmaxf(by1[m], py1), 0.f);
            float inter = iw * ih;
            float iou = __fdividef(inter, barea[m] + ab - inter);
            if (iou > bv) { bv = iou; bm = m; }                      // first-max (argmax axis=0)
            if (iou > bestv[m]) { bestv[m] = iou; besti[m] = p; }    // first-max within thread
        }
        ov_prior[p]  = bv;
        obj_prior[p] = (unsigned char)bm;
    }

    // Reduce per-object bests: warp shuffle, then cross-warp (tie -> smallest prior index)
#pragma unroll
    for (int m = 0; m < MM; m++) {
        float v = bestv[m]; int ix = besti[m];
#pragma unroll
        for (int o = 16; o; o >>= 1) {
            float v2 = __shfl_down_sync(0xffffffffu, v, o);
            int   i2 = __shfl_down_sync(0xffffffffu, ix, o);
            if (v2 > v || (v2 == v && i2 < ix)) { v = v2; ix = i2; }
        }
        if (lane == 0) { wbv[m * NW + (tid >> 5)] = v; wbi[m * NW + (tid >> 5)] = ix; }
    }
    __syncthreads();
    if (tid < MM) {
        float v = wbv[tid * NW]; int ix = wbi[tid * NW];
        for (int w = 1; w < NW; w++) {
            float v2 = wbv[tid * NW + w]; int i2 = wbi[tid * NW + w];
            if (v2 > v || (v2 == v && i2 < ix)) { v = v2; ix = i2; }
        }
        sprior_obj[tid] = ix;
    }
    __syncthreads();
    // Bipartite overrides (sequential m: last object wins on duplicate priors)
    if (tid == 0) {
        for (int m = 0; m < MM; m++) {
            int p = sprior_obj[m];
            obj_prior[p] = (unsigned char)m;
            ov_prior[p]  = 1.0f;
        }
    }
    __syncthreads();

    // ---- Pass 2: labels, BCE, L1, conf_neg ----
    int   npos_loc = 0;
    float cpos_loc = 0.f, l1_loc = 0.f;

    for (int p = tid; p < PP; p += NT) {
        int m   = obj_prior[p];
        int lab = (ov_prior[p] < 0.5f) ? 0 : slabels[m];

        const float* sc = pscores + ((size_t)i * PP + p) * CC;
        float s0 = sc[0], s1 = sc[1], s2 = sc[2];
        // target: lab 0->[1,0,0] 1->[0,1,0] 2->[0,0,1] 3->[0,1,1]
        float t0 = (lab == 0) ? 1.f : 0.f;
        float t1 = (lab == 1 || lab == 3) ? 1.f : 0.f;
        float t2 = (lab == 2 || lab == 3) ? 1.f : 0.f;
        float bce = (softplusf(s0) - s0 * t0)
                  + (softplusf(s1) - s1 * t1)
                  + (softplusf(s2) - s2 * t2);

        if (lab > 0) {
            npos_loc++;
            cpos_loc += bce;
            conf_neg[p] = 0.f;
            const float* pl = plocs + ((size_t)i * PP + p) * 4;
            float4 pr = ((const float4*)priors)[p];
            float cx = (sboxes[m * 4 + 0] + sboxes[m * 4 + 2]) * 0.5f;
            float cy = (sboxes[m * 4 + 1] + sboxes[m * 4 + 3]) * 0.5f;
            float w  = sboxes[m * 4 + 2] - sboxes[m * 4 + 0];
            float h  = sboxes[m * 4 + 3] - sboxes[m * 4 + 1];
            float g0 = __fdividef(10.0f * (cx - pr.x), pr.z);
            float g1 = __fdividef(10.0f * (cy - pr.y), pr.w);
            float g2 = __logf(__fdividef(w, pr.z)) * 5.0f;
            float g3 = __logf(__fdividef(h, pr.w)) * 5.0f;
            l1_loc += fabsf(pl[0] - g0) + fabsf(pl[1] - g1)
                    + fabsf(pl[2] - g2) + fabsf(pl[3] - g3);
        } else {
            conf_neg[p] = bce;
        }
    }

    // Block reductions: REDUX/shfl per warp, one smem atomic per warp, ONE barrier.
    {
        int nf = __reduce_add_sync(0xffffffffu, npos_loc);
        float cf = cpos_loc, lf = l1_loc;
#pragma unroll
        for (int o = 16; o; o >>= 1) {
            cf += __shfl_down_sync(0xffffffffu, cf, o);
            lf += __shfl_down_sync(0xffffffffu, lf, o);
        }
        if (lane == 0) {
            atomicAdd(&slotsI[32], nf);
            atomicAdd(&slotsF[0], cf);
            atomicAdd(&slotsF[1], lf);
        }
    }
    __syncthreads();  // also orders conf_neg writes before the scans below
    int   npos_i = slotsI[32];
    float cpos_i = slotsF[0];
    float l1_i   = slotsF[1];

    // ---- Hard-negative mining: exact top-k sum via bitwise binary search ----
    int k = 3 * npos_i;
    if (k > PP) k = PP;
    float hardneg = 0.f;
    if (k > 0) {
        unsigned lo = 0u, hi = 0x7f800000u;  // [0, +inf): conf_neg >= 0, finite
        int it = 0;
        while (hi - lo > 1u) {
            unsigned mid = (lo + hi) >> 1;
            float tv = __uint_as_float(mid);
            int c = 0;
            for (int p = tid; p < PP; p += NT) c += (conf_neg[p] >= tv) ? 1 : 0;
            c = __reduce_add_sync(0xffffffffu, c);
            if (lane == 0) atomicAdd(&slotsI[it], c);
            __syncthreads();
            c = slotsI[it]; it++;
            if (c >= k) lo = mid; else hi = mid;
        }
        float t = __uint_as_float(lo);  // exact k-th largest value
        int cgt = 0; float sgt = 0.f;
        for (int p = tid; p < PP; p += NT) {
            float v = conf_neg[p];
            if (v > t) { cgt++; sgt += v; }
        }
        cgt = __reduce_add_sync(0xffffffffu, cgt);
#pragma unroll
        for (int o = 16; o; o >>= 1) sgt += __shfl_down_sync(0xffffffffu, sgt, o);
        if (lane == 0) {
            atomicAdd(&slotsI[33], cgt);
            atomicAdd(&slotsF[2], sgt);
        }
        __syncthreads();
        cgt = slotsI[33];
        sgt = slotsF[2];
        hardneg = sgt + t * (float)(k - cgt);  // ties at t exactly reproduce sorted top-k
    }

    if (tid == 0) {
        atomicAdd(&g_conf_sum, (double)(cpos_i + hardneg));
        atomicAdd(&g_l1_sum,   (double)l1_i);
        atomicAdd(&g_npos,     npos_i);
        if (out_size >= 3 + BB) out[3 + i] = (float)npos_i;
    }
}

__global__ void mbl_fin_kernel(float* __restrict__ out, int out_size) {
    double npt  = (double)g_npos;
    double conf = g_conf_sum / (1e-10 + npt);
    double loc  = (g_npos > 0) ? (g_l1_sum / (4.0 * fmax(npt, 1.0))) : 0.0;
    out[0] = (float)(conf + loc);
    if (out_size > 1) out[1] = (float)conf;
    if (out_size > 2) out[2] = (float)loc;
}

extern "C" void kernel_launch(void* const* d_in, const int* in_sizes, int n_in,
                              void* d_out, int out_size) {
    const float* plocs   = (const float*)d_in[0];
    const float* pscores = (const float*)d_in[1];
    const float* boxes   = (const float*)d_in[2];
    const int*   labels  = (const int*)d_in[3];
    const float* priors  = (const float*)d_in[4];
    float* out = (float*)d_out;

    size_t shbytes = (size_t)PP * 4 * 2                          // conf_neg + ov_prior
                   + 4 * (64 + 16 + MM * NW * 2 + 16 + 40 + 8)   // boxes/labels/reduce scratch
                   + PP;                                          // obj_prior bytes
    cudaFuncSetAttribute(mbl_kernel, cudaFuncAttributeMaxDynamicSharedMemorySize,
                         (int)shbytes);

    mbl_init_kernel<<<1, 1>>>();
    mbl_kernel<<<BB, NT, shbytes>>>(plocs, pscores, boxes, labels, priors, out, out_size);
    mbl_fin_kernel<<<1, 1>>>(out, out_size);
}